// round 12
// baseline (speedup 1.0000x reference)
#include <cuda_runtime.h>
#include <cstdint>

// MHSA without softmax, 5 kernels:
//  K0a/K0b: pre-round X, W to tf32 bit patterns (removes cvt from GEMM loop)
//  K1 fused_gemm (TF32 mma.sync):
//     - Q-CTAs (bx<4): write q[4096][512] + column-sum partials (qsumpart)
//     - KV-CTAs (bx>=4, head h): compute [k_h | v_h] tile, write k, and
//       reduce Mpart[rowblk,h] = K_tile^T V_tile in-block (v never hits DRAM)
//  K2 reduce_parts: g_M = sum Mpart, g_qsum = sum qsumpart  (fixed order)
//  K3 output_coarse: out = scale * q @ M_h ; coarse = scale * qsum_h . k_h[n]
// d_out: [coarse 8*4096][output 8*4096*64]

#define NTOK 4096
#define E3   1536
#define NRB  32                 // 32 row-blocks of 128 tokens

__device__ float g_Xc[512 * NTOK];    // tf32-rounded X
__device__ float g_Wc[512 * E3];      // tf32-rounded W
__device__ float g_q[NTOK * 512];
__device__ float g_k[NTOK * 512];
__device__ float g_Mpart[NRB * 8 * 64 * 64];
__device__ float g_qsumpart[NRB * 512];
__device__ float g_M[8 * 64 * 64];
__device__ float g_qsum[512];

// ---------------------------------------------------------------------------
__device__ __forceinline__ uint32_t smem_u32(const void* p) {
    uint32_t a;
    asm("{ .reg .u64 t; cvta.to.shared.u64 t, %1; cvt.u32.u64 %0, t; }" : "=r"(a) : "l"(p));
    return a;
}
#define CP_ASYNC16(sa, gp) \
    asm volatile("cp.async.cg.shared.global [%0], [%1], 16;" :: "r"(sa), "l"(gp))
#define CP_COMMIT() asm volatile("cp.async.commit_group;")
#define CP_WAIT1()  asm volatile("cp.async.wait_group 1;")
#define CP_WAIT0()  asm volatile("cp.async.wait_group 0;")

__device__ __forceinline__ uint32_t f2tf32(float f) {
    uint32_t r;
    asm("cvt.rna.tf32.f32 %0, %1;" : "=r"(r) : "f"(f));
    return r;
}
#define MMA_TF32(d, a, b0, b1) \
    asm volatile("mma.sync.aligned.m16n8k8.row.col.f32.tf32.tf32.f32 " \
        "{%0,%1,%2,%3},{%4,%5,%6,%7},{%8,%9},{%0,%1,%2,%3};" \
        : "+f"((d)[0]), "+f"((d)[1]), "+f"((d)[2]), "+f"((d)[3]) \
        : "r"((a)[0]), "r"((a)[1]), "r"((a)[2]), "r"((a)[3]), "r"(b0), "r"(b1))

// ---------------------------------------------------------------------------
// K0: elementwise tf32 pre-round (float4 in/out).
// ---------------------------------------------------------------------------
__global__ __launch_bounds__(256)
void cvt_tf32_kernel(const float* __restrict__ src, float* __restrict__ dst)
{
    const int i = (blockIdx.x * 256 + threadIdx.x) * 4;
    const float4 v = *(const float4*)&src[i];
    float4 o;
    o.x = __uint_as_float(f2tf32(v.x));
    o.y = __uint_as_float(f2tf32(v.y));
    o.z = __uint_as_float(f2tf32(v.z));
    o.w = __uint_as_float(f2tf32(v.w));
    *(float4*)&dst[i] = o;
}

// ---------------------------------------------------------------------------
// K1: fused TF32 GEMM + per-tile reductions.
// CTA 128x128, 8 warps (2Mx4N, warp 64x32), BK=32, 3-stage cp.async,
// one __syncthreads per K-iteration. Operands pre-rounded -> no cvt in loop.
// smem stride 136 floats (conflict-free fragment LDS).
// ---------------------------------------------------------------------------
#define SST         136
#define STAGE_FLT   (2 * 32 * SST)              // A then B: 8704 floats
#define STAGE_BYT   (STAGE_FLT * 4)             // 34816 B
#define GEMM_SMEM   (3 * STAGE_BYT)             // 104448 B

__global__ __launch_bounds__(256)
void fused_gemm(const float* __restrict__ bias)
{
    extern __shared__ float sm[];
    const uint32_t smb = smem_u32(sm);
    const int tid = threadIdx.x;
    const int lane = tid & 31, wid = tid >> 5;
    const int bx = blockIdx.x;               // 0..11
    const int by = blockIdx.y;               // 0..31
    const int bm = by * 128;
    const bool isQ = (bx < 4);
    const int bn = isQ ? bx * 128 : 0;       // q col base
    const int hh = bx - 4;                   // head for kv-CTAs
    const int wm = (wid & 1) * 64, wn = (wid >> 1) * 32;

    float acc[4][4][4];
#pragma unroll
    for (int i = 0; i < 4; i++)
#pragma unroll
        for (int j = 0; j < 4; j++)
#pragma unroll
            for (int r = 0; r < 4; r++) acc[i][j][r] = 0.0f;

    auto ldstage = [&](int it, int s) {
        const int k0 = it * 32;
        const uint32_t sa = smb + s * STAGE_BYT;
#pragma unroll
        for (int i = 0; i < 4; i++) {
            const int idx = i * 256 + tid;
            const int row = idx >> 5;             // 0..31
            const int c   = (idx & 31) * 4;       // 0..124
            CP_ASYNC16(sa + (uint32_t)(row * SST + c) * 4,
                       g_Xc + (size_t)(k0 + row) * NTOK + bm + c);
        }
#pragma unroll
        for (int i = 0; i < 4; i++) {
            const int idx = i * 256 + tid;
            const int row = idx >> 5;
            const int c   = (idx & 31) * 4;
            const int gc  = isQ ? (bn + c)
                                : (c < 64 ? 512 + 64 * hh + c : 960 + 64 * hh + c);
            CP_ASYNC16(sa + (uint32_t)(32 * SST + row * SST + c) * 4,
                       g_Wc + (size_t)(k0 + row) * E3 + gc);
        }
        CP_COMMIT();
    };

    ldstage(0, 0);
    ldstage(1, 1);

    for (int it = 0; it < 16; ++it) {
        if (it >= 15) { CP_WAIT0(); } else { CP_WAIT1(); }
        __syncthreads();
        if (it + 2 < 16) ldstage(it + 2, (it + 2) % 3);

        const uint32_t* As = (const uint32_t*)(sm + (it % 3) * STAGE_FLT);
        const uint32_t* Bs = As + 32 * SST;

#pragma unroll
        for (int kk = 0; kk < 4; kk++) {
            const int kb = kk * 8 + (lane & 3);
            uint32_t a[4][4], b[4][2];
#pragma unroll
            for (int mt = 0; mt < 4; mt++) {
                const int m = wm + mt * 16 + (lane >> 2);
                a[mt][0] = As[kb * SST + m];
                a[mt][1] = As[kb * SST + m + 8];
                a[mt][2] = As[(kb + 4) * SST + m];
                a[mt][3] = As[(kb + 4) * SST + m + 8];
            }
#pragma unroll
            for (int n8 = 0; n8 < 4; n8++) {
                const int n = wn + n8 * 8 + (lane >> 2);
                b[n8][0] = Bs[kb * SST + n];
                b[n8][1] = Bs[(kb + 4) * SST + n];
            }
#pragma unroll
            for (int mt = 0; mt < 4; mt++)
#pragma unroll
                for (int n8 = 0; n8 < 4; n8++)
                    MMA_TF32(acc[mt][n8], a[mt], b[n8][0], b[n8][1]);
        }
    }
    __syncthreads();   // mainloop smem now reusable

    const int er = lane >> 2, ec = (lane & 3) * 2;

    if (isQ) {
        // ---- write q (+bias) ----
#pragma unroll
        for (int n8 = 0; n8 < 4; n8++) {
            const int c = wn + n8 * 8 + ec;
            const float2 bv = *(const float2*)&bias[bn + c];
#pragma unroll
            for (int mt = 0; mt < 4; mt++) {
                const int r = bm + wm + mt * 16 + er;
                float2 o0 = { acc[mt][n8][0] + bv.x, acc[mt][n8][1] + bv.y };
                *(float2*)&g_q[(size_t)r * 512 + bn + c] = o0;
                float2 o1 = { acc[mt][n8][2] + bv.x, acc[mt][n8][3] + bv.y };
                *(float2*)&g_q[(size_t)(r + 8) * 512 + bn + c] = o1;
            }
        }
        // ---- column partial sums (qsum over this 128-token block) ----
        float s0[4], s1[4];
#pragma unroll
        for (int n8 = 0; n8 < 4; n8++) {
            s0[n8] = 0.0f; s1[n8] = 0.0f;
#pragma unroll
            for (int mt = 0; mt < 4; mt++) {
                s0[n8] += acc[mt][n8][0] + acc[mt][n8][2];
                s1[n8] += acc[mt][n8][1] + acc[mt][n8][3];
            }
#pragma unroll
            for (int msk = 16; msk >= 4; msk >>= 1) {
                s0[n8] += __shfl_xor_sync(0xffffffff, s0[n8], msk);
                s1[n8] += __shfl_xor_sync(0xffffffff, s1[n8], msk);
            }
        }
        float* qsp = sm;                 // [2][128]
        if (lane < 4) {
#pragma unroll
            for (int n8 = 0; n8 < 4; n8++) {
                const int c = wn + n8 * 8 + lane * 2;
                qsp[(wid & 1) * 128 + c]     = s0[n8];
                qsp[(wid & 1) * 128 + c + 1] = s1[n8];
            }
        }
        __syncthreads();
        if (tid < 128)
            g_qsumpart[by * 512 + bn + tid] =
                qsp[tid] + qsp[128 + tid] + 128.0f * bias[bn + tid];
    } else {
        // ---- stage C (+bias) into smem: Cs[128][136], cols [k_h | v_h] ----
        float* Cs = sm;
#pragma unroll
        for (int n8 = 0; n8 < 4; n8++) {
            const int c = wn + n8 * 8 + ec;
            const int gc = (c < 64) ? 512 + 64 * hh + c : 960 + 64 * hh + c;
            const float2 bv = *(const float2*)&bias[gc];
#pragma unroll
            for (int mt = 0; mt < 4; mt++) {
                const int r = wm + mt * 16 + er;
                Cs[r * SST + c]           = acc[mt][n8][0] + bv.x;
                Cs[r * SST + c + 1]       = acc[mt][n8][1] + bv.y;
                Cs[(r + 8) * SST + c]     = acc[mt][n8][2] + bv.x;
                Cs[(r + 8) * SST + c + 1] = acc[mt][n8][3] + bv.y;
            }
        }
        __syncthreads();
        // ---- write k half to g_k ----
#pragma unroll
        for (int i = 0; i < 8; i++) {
            const int idx = i * 256 + tid;        // 2048 float4s
            const int row = idx >> 4, c = (idx & 15) * 4;
            *(float4*)&g_k[(size_t)(bm + row) * 512 + hh * 64 + c] =
                *(const float4*)&Cs[row * SST + c];
        }
        // ---- Mpart = K_tile^T V_tile over 128 tokens; thread tile 4x4 ----
        const int d1b = (tid >> 4) << 2;
        const int d2b = (tid & 15) << 2;
        float m2[4][4];
#pragma unroll
        for (int i = 0; i < 4; i++)
#pragma unroll
            for (int j = 0; j < 4; j++) m2[i][j] = 0.0f;

#pragma unroll 4
        for (int n = 0; n < 128; n++) {
            const float4 kv = *(const float4*)&Cs[n * SST + d1b];
            const float4 vv = *(const float4*)&Cs[n * SST + 64 + d2b];
            m2[0][0] = fmaf(kv.x, vv.x, m2[0][0]);
            m2[0][1] = fmaf(kv.x, vv.y, m2[0][1]);
            m2[0][2] = fmaf(kv.x, vv.z, m2[0][2]);
            m2[0][3] = fmaf(kv.x, vv.w, m2[0][3]);
            m2[1][0] = fmaf(kv.y, vv.x, m2[1][0]);
            m2[1][1] = fmaf(kv.y, vv.y, m2[1][1]);
            m2[1][2] = fmaf(kv.y, vv.z, m2[1][2]);
            m2[1][3] = fmaf(kv.y, vv.w, m2[1][3]);
            m2[2][0] = fmaf(kv.z, vv.x, m2[2][0]);
            m2[2][1] = fmaf(kv.z, vv.y, m2[2][1]);
            m2[2][2] = fmaf(kv.z, vv.z, m2[2][2]);
            m2[2][3] = fmaf(kv.z, vv.w, m2[2][3]);
            m2[3][0] = fmaf(kv.w, vv.x, m2[3][0]);
            m2[3][1] = fmaf(kv.w, vv.y, m2[3][1]);
            m2[3][2] = fmaf(kv.w, vv.z, m2[3][2]);
            m2[3][3] = fmaf(kv.w, vv.w, m2[3][3]);
        }
#pragma unroll
        for (int i = 0; i < 4; i++) {
            float4 o = { m2[i][0], m2[i][1], m2[i][2], m2[i][3] };
            *(float4*)&g_Mpart[((by * 8 + hh) * 64 + d1b + i) * 64 + d2b] = o;
        }
    }
}

// ---------------------------------------------------------------------------
// K2: deterministic final reductions.
// ---------------------------------------------------------------------------
__global__ __launch_bounds__(256)
void reduce_parts_kernel()
{
    if (blockIdx.x < 128) {
        const int idx = blockIdx.x * 256 + threadIdx.x;   // 0..32767
        float sum = 0.0f;
#pragma unroll
        for (int c = 0; c < NRB; c++) sum += g_Mpart[c * 32768 + idx];
        g_M[idx] = sum;
    } else {
        for (int t = threadIdx.x; t < 512; t += 256) {
            float sum = 0.0f;
#pragma unroll
            for (int c = 0; c < NRB; c++) sum += g_qsumpart[c * 512 + t];
            g_qsum[t] = sum;
        }
    }
}

// ---------------------------------------------------------------------------
// K3: output + coarse. grid (32, 8), 128 threads, thread tile 8n x 8d2.
//   out[h,n,d2]  = scale * sum_d1 q_h[n,d1] * M_h[d1,d2]
//   coarse[h,n]  = scale * dot(qsum_h, k_h[n])
// ---------------------------------------------------------------------------
#define OUT_SMEM ((4096 + 8192 + 64) * 4)

__global__ __launch_bounds__(128)
void output_coarse_kernel(float* __restrict__ out)
{
    extern __shared__ float osm[];
    float (*Ms)[64] = (float(*)[64])osm;             // 64 x 64
    float (*qs)[64] = (float(*)[64])(osm + 4096);    // 128 x 64
    float* qsh = osm + 12288;                        // 64

    const int n0 = blockIdx.x * 128;
    const int h  = blockIdx.y;
    const int t  = threadIdx.x;

#pragma unroll
    for (int r = 0; r < 8; r++) {
        const int l = t + r * 128;
        *(float4*)&Ms[l >> 4][(l & 15) * 4] =
            *(const float4*)&g_M[h * 4096 + (l >> 4) * 64 + (l & 15) * 4];
    }
#pragma unroll
    for (int r = 0; r < 16; r++) {
        const int l = t + r * 128;
        *(float4*)&qs[l >> 4][(l & 15) * 4] =
            *(const float4*)&g_q[(size_t)(n0 + (l >> 4)) * 512 + h * 64 + (l & 15) * 4];
    }
    if (t < 64) qsh[t] = g_qsum[h * 64 + t];
    __syncthreads();

    const int tx = t & 7;        // d2 group (8 wide)
    const int ty = t >> 3;       // n group (8 rows)

    float acc[8][8];
#pragma unroll
    for (int i = 0; i < 8; i++)
#pragma unroll
        for (int j = 0; j < 8; j++) acc[i][j] = 0.0f;

#pragma unroll
    for (int d1 = 0; d1 < 64; d1++) {
        const float4 m0 = *(const float4*)&Ms[d1][tx * 8];
        const float4 m1 = *(const float4*)&Ms[d1][tx * 8 + 4];
#pragma unroll
        for (int i = 0; i < 8; i++) {
            const float qv = qs[ty * 8 + i][d1];
            acc[i][0] = fmaf(qv, m0.x, acc[i][0]);
            acc[i][1] = fmaf(qv, m0.y, acc[i][1]);
            acc[i][2] = fmaf(qv, m0.z, acc[i][2]);
            acc[i][3] = fmaf(qv, m0.w, acc[i][3]);
            acc[i][4] = fmaf(qv, m1.x, acc[i][4]);
            acc[i][5] = fmaf(qv, m1.y, acc[i][5]);
            acc[i][6] = fmaf(qv, m1.z, acc[i][6]);
            acc[i][7] = fmaf(qv, m1.w, acc[i][7]);
        }
    }

#pragma unroll
    for (int i = 0; i < 8; i++) {
        const int n = n0 + ty * 8 + i;
        float* ob = &out[32768 + (size_t)((h << 12) + n) * 64 + tx * 8];
        float4 o0 = { acc[i][0] * 0.125f, acc[i][1] * 0.125f,
                      acc[i][2] * 0.125f, acc[i][3] * 0.125f };
        float4 o1 = { acc[i][4] * 0.125f, acc[i][5] * 0.125f,
                      acc[i][6] * 0.125f, acc[i][7] * 0.125f };
        *(float4*)ob = o0;
        *(float4*)(ob + 4) = o1;
    }

    // coarse: one n per thread
    {
        const int n = n0 + t;
        const float4* kp = (const float4*)&g_k[(size_t)n * 512 + h * 64];
        float c = 0.0f;
#pragma unroll
        for (int i = 0; i < 16; i++) {
            const float4 k4 = kp[i];
            const float4 q4 = *(const float4*)&qsh[i * 4];
            c = fmaf(q4.x, k4.x, c); c = fmaf(q4.y, k4.y, c);
            c = fmaf(q4.z, k4.z, c); c = fmaf(q4.w, k4.w, c);
        }
        out[(h << 12) + n] = c * 0.125f;
    }
}

// ---------------------------------------------------------------------------
extern "C" void kernel_launch(void* const* d_in, const int* in_sizes, int n_in,
                              void* d_out, int out_size)
{
    const float* x  = (const float*)d_in[0];   // [512, 4096]
    const float* Wq = (const float*)d_in[1];   // [512, 1536]
    const float* bq = (const float*)d_in[2];   // [1536]
    float* out = (float*)d_out;
    (void)in_sizes; (void)n_in; (void)out_size;

    cudaFuncSetAttribute(fused_gemm, cudaFuncAttributeMaxDynamicSharedMemorySize, GEMM_SMEM);
    cudaFuncSetAttribute(output_coarse_kernel, cudaFuncAttributeMaxDynamicSharedMemorySize, OUT_SMEM);

    float* gXc; cudaGetSymbolAddress((void**)&gXc, g_Xc);
    float* gWc; cudaGetSymbolAddress((void**)&gWc, g_Wc);

    cvt_tf32_kernel<<<2048, 256>>>(x, gXc);    // 512*4096 / 1024
    cvt_tf32_kernel<<<768, 256>>>(Wq, gWc);    // 512*1536 / 1024

    fused_gemm<<<dim3(12, 32), 256, GEMM_SMEM>>>(bq);
    reduce_parts_kernel<<<129, 256>>>();
    output_coarse_kernel<<<dim3(32, 8), 128, OUT_SMEM>>>(out);
}

// round 14
// speedup vs baseline: 1.0008x; 1.0008x over previous
#include <cuda_runtime.h>
#include <cstdint>

// MHSA without softmax, 4 kernels:
//  K0 cvt: pre-round X and W to tf32 bit patterns (single launch)
//  K1 fused_gemm (TF32 mma.sync, BK=16, 4-stage cp.async, 2 CTAs/SM):
//     - Q-CTAs (bx<4): write q[4096][512] + column-sum partials (qsumpart)
//     - KV-CTAs (bx>=4, head h): compute [k_h | v_h] tile, write k, and
//       reduce Mpart[rowblk,h] = K_tile^T V_tile in-block (v never hits DRAM)
//  K2 reduce_parts: g_M = sum Mpart, g_qsum = sum qsumpart  (fixed order)
//  K3 output_coarse: out = scale * q @ M_h ; coarse = scale * qsum_h . k_h[n]
// d_out: [coarse 8*4096][output 8*4096*64]

#define NTOK 4096
#define E3   1536
#define NRB  32                 // 32 row-blocks of 128 tokens

__device__ float g_Xc[512 * NTOK];    // tf32-rounded X
__device__ float g_Wc[512 * E3];      // tf32-rounded W
__device__ float g_q[NTOK * 512];
__device__ float g_k[NTOK * 512];
__device__ float g_Mpart[NRB * 8 * 64 * 64];
__device__ float g_qsumpart[NRB * 512];
__device__ float g_M[8 * 64 * 64];
__device__ float g_qsum[512];

// ---------------------------------------------------------------------------
__device__ __forceinline__ uint32_t smem_u32(const void* p) {
    uint32_t a;
    asm("{ .reg .u64 t; cvta.to.shared.u64 t, %1; cvt.u32.u64 %0, t; }" : "=r"(a) : "l"(p));
    return a;
}
#define CP_ASYNC16(sa, gp) \
    asm volatile("cp.async.cg.shared.global [%0], [%1], 16;" :: "r"(sa), "l"(gp))
#define CP_COMMIT() asm volatile("cp.async.commit_group;")
#define CP_WAIT2()  asm volatile("cp.async.wait_group 2;")
#define CP_WAIT0()  asm volatile("cp.async.wait_group 0;")

__device__ __forceinline__ uint32_t f2tf32(float f) {
    uint32_t r;
    asm("cvt.rna.tf32.f32 %0, %1;" : "=r"(r) : "f"(f));
    return r;
}
#define MMA_TF32(d, a, b0, b1) \
    asm volatile("mma.sync.aligned.m16n8k8.row.col.f32.tf32.tf32.f32 " \
        "{%0,%1,%2,%3},{%4,%5,%6,%7},{%8,%9},{%0,%1,%2,%3};" \
        : "+f"((d)[0]), "+f"((d)[1]), "+f"((d)[2]), "+f"((d)[3]) \
        : "r"((a)[0]), "r"((a)[1]), "r"((a)[2]), "r"((a)[3]), "r"(b0), "r"(b1))

// ---------------------------------------------------------------------------
// K0: elementwise tf32 pre-round of X then W (one launch).
// X: 2048 blocks (524288 float4), W: 768 blocks (196608 float4).
// ---------------------------------------------------------------------------
__global__ __launch_bounds__(256)
void cvt_tf32_kernel(const float* __restrict__ X, const float* __restrict__ W)
{
    const int b = blockIdx.x;
    const float* src;
    float* dst;
    int i;
    if (b < 2048) {
        src = X; dst = g_Xc; i = (b * 256 + threadIdx.x) * 4;
    } else {
        src = W; dst = g_Wc; i = ((b - 2048) * 256 + threadIdx.x) * 4;
    }
    const float4 v = *(const float4*)&src[i];
    float4 o;
    o.x = __uint_as_float(f2tf32(v.x));
    o.y = __uint_as_float(f2tf32(v.y));
    o.z = __uint_as_float(f2tf32(v.z));
    o.w = __uint_as_float(f2tf32(v.w));
    *(float4*)&dst[i] = o;
}

// ---------------------------------------------------------------------------
// K1: fused TF32 GEMM + per-tile reductions.
// CTA 128x128, 8 warps (2Mx4N, warp 64x32), BK=16, 4-stage cp.async,
// one __syncthreads per K-iteration, 69632 B smem -> 2 CTAs/SM.
// smem stride 136 floats (conflict-free fragment LDS).
// ---------------------------------------------------------------------------
#define SST         136
#define STAGE_FLT   (2 * 16 * SST)              // A then B: 4352 floats
#define STAGE_BYT   (STAGE_FLT * 4)             // 17408 B
#define GEMM_SMEM   (4 * STAGE_BYT)             // 69632 B (== Cs[128][136])

__global__ __launch_bounds__(256, 2)
void fused_gemm(const float* __restrict__ bias)
{
    extern __shared__ float sm[];
    const uint32_t smb = smem_u32(sm);
    const int tid = threadIdx.x;
    const int lane = tid & 31, wid = tid >> 5;
    const int bx = blockIdx.x;               // 0..11
    const int by = blockIdx.y;               // 0..31
    const int bm = by * 128;
    const bool isQ = (bx < 4);
    const int bn = isQ ? bx * 128 : 0;       // q col base
    const int hh = bx - 4;                   // head for kv-CTAs
    const int wm = (wid & 1) * 64, wn = (wid >> 1) * 32;

    float acc[4][4][4];
#pragma unroll
    for (int i = 0; i < 4; i++)
#pragma unroll
        for (int j = 0; j < 4; j++)
#pragma unroll
            for (int r = 0; r < 4; r++) acc[i][j][r] = 0.0f;

    auto ldstage = [&](int it, int s) {
        const int k0 = it * 16;
        const uint32_t sa = smb + s * STAGE_BYT;
#pragma unroll
        for (int i = 0; i < 2; i++) {
            const int idx = i * 256 + tid;
            const int row = idx >> 5;             // 0..15
            const int c   = (idx & 31) * 4;       // 0..124
            CP_ASYNC16(sa + (uint32_t)(row * SST + c) * 4,
                       g_Xc + (size_t)(k0 + row) * NTOK + bm + c);
        }
#pragma unroll
        for (int i = 0; i < 2; i++) {
            const int idx = i * 256 + tid;
            const int row = idx >> 5;
            const int c   = (idx & 31) * 4;
            const int gc  = isQ ? (bn + c)
                                : (c < 64 ? 512 + 64 * hh + c : 960 + 64 * hh + c);
            CP_ASYNC16(sa + (uint32_t)(16 * SST + row * SST + c) * 4,
                       g_Wc + (size_t)(k0 + row) * E3 + gc);
        }
        CP_COMMIT();
    };

    ldstage(0, 0);
    ldstage(1, 1);
    ldstage(2, 2);

    for (int it = 0; it < 32; ++it) {
        if (it >= 30) { CP_WAIT0(); } else { CP_WAIT2(); }
        __syncthreads();                            // all warps done with it-1
        if (it + 3 < 32) ldstage(it + 3, (it + 3) & 3);

        const uint32_t* As = (const uint32_t*)(sm + (it & 3) * STAGE_FLT);
        const uint32_t* Bs = As + 16 * SST;

#pragma unroll
        for (int kk = 0; kk < 2; kk++) {
            const int kb = kk * 8 + (lane & 3);
            uint32_t a[4][4], b[4][2];
#pragma unroll
            for (int mt = 0; mt < 4; mt++) {
                const int m = wm + mt * 16 + (lane >> 2);
                a[mt][0] = As[kb * SST + m];
                a[mt][1] = As[kb * SST + m + 8];
                a[mt][2] = As[(kb + 4) * SST + m];
                a[mt][3] = As[(kb + 4) * SST + m + 8];
            }
#pragma unroll
            for (int n8 = 0; n8 < 4; n8++) {
                const int n = wn + n8 * 8 + (lane >> 2);
                b[n8][0] = Bs[kb * SST + n];
                b[n8][1] = Bs[(kb + 4) * SST + n];
            }
#pragma unroll
            for (int mt = 0; mt < 4; mt++)
#pragma unroll
                for (int n8 = 0; n8 < 4; n8++)
                    MMA_TF32(acc[mt][n8], a[mt], b[n8][0], b[n8][1]);
        }
    }
    __syncthreads();   // mainloop smem now reusable

    const int er = lane >> 2, ec = (lane & 3) * 2;

    if (isQ) {
        // ---- write q (+bias) ----
#pragma unroll
        for (int n8 = 0; n8 < 4; n8++) {
            const int c = wn + n8 * 8 + ec;
            const float2 bv = *(const float2*)&bias[bn + c];
#pragma unroll
            for (int mt = 0; mt < 4; mt++) {
                const int r = bm + wm + mt * 16 + er;
                float2 o0 = { acc[mt][n8][0] + bv.x, acc[mt][n8][1] + bv.y };
                *(float2*)&g_q[(size_t)r * 512 + bn + c] = o0;
                float2 o1 = { acc[mt][n8][2] + bv.x, acc[mt][n8][3] + bv.y };
                *(float2*)&g_q[(size_t)(r + 8) * 512 + bn + c] = o1;
            }
        }
        // ---- column partial sums (qsum over this 128-token block) ----
        float s0[4], s1[4];
#pragma unroll
        for (int n8 = 0; n8 < 4; n8++) {
            s0[n8] = 0.0f; s1[n8] = 0.0f;
#pragma unroll
            for (int mt = 0; mt < 4; mt++) {
                s0[n8] += acc[mt][n8][0] + acc[mt][n8][2];
                s1[n8] += acc[mt][n8][1] + acc[mt][n8][3];
            }
#pragma unroll
            for (int msk = 16; msk >= 4; msk >>= 1) {
                s0[n8] += __shfl_xor_sync(0xffffffff, s0[n8], msk);
                s1[n8] += __shfl_xor_sync(0xffffffff, s1[n8], msk);
            }
        }
        float* qsp = sm;                 // [2][128]
        if (lane < 4) {
#pragma unroll
            for (int n8 = 0; n8 < 4; n8++) {
                const int c = wn + n8 * 8 + lane * 2;
                qsp[(wid & 1) * 128 + c]     = s0[n8];
                qsp[(wid & 1) * 128 + c + 1] = s1[n8];
            }
        }
        __syncthreads();
        if (tid < 128)
            g_qsumpart[by * 512 + bn + tid] =
                qsp[tid] + qsp[128 + tid] + 128.0f * bias[bn + tid];
    } else {
        // ---- stage C (+bias) into smem: Cs[128][136], cols [k_h | v_h] ----
        float* Cs = sm;
#pragma unroll
        for (int n8 = 0; n8 < 4; n8++) {
            const int c = wn + n8 * 8 + ec;
            const int gc = (c < 64) ? 512 + 64 * hh + c : 960 + 64 * hh + c;
            const float2 bv = *(const float2*)&bias[gc];
#pragma unroll
            for (int mt = 0; mt < 4; mt++) {
                const int r = wm + mt * 16 + er;
                Cs[r * SST + c]           = acc[mt][n8][0] + bv.x;
                Cs[r * SST + c + 1]       = acc[mt][n8][1] + bv.y;
                Cs[(r + 8) * SST + c]     = acc[mt][n8][2] + bv.x;
                Cs[(r + 8) * SST + c + 1] = acc[mt][n8][3] + bv.y;
            }
        }
        __syncthreads();
        // ---- write k half to g_k ----
#pragma unroll
        for (int i = 0; i < 8; i++) {
            const int idx = i * 256 + tid;        // 2048 float4s
            const int row = idx >> 4, c = (idx & 15) * 4;
            *(float4*)&g_k[(size_t)(bm + row) * 512 + hh * 64 + c] =
                *(const float4*)&Cs[row * SST + c];
        }
        // ---- Mpart = K_tile^T V_tile over 128 tokens; thread tile 4x4 ----
        const int d1b = (tid >> 4) << 2;
        const int d2b = (tid & 15) << 2;
        float m2[4][4];
#pragma unroll
        for (int i = 0; i < 4; i++)
#pragma unroll
            for (int j = 0; j < 4; j++) m2[i][j] = 0.0f;

#pragma unroll 4
        for (int n = 0; n < 128; n++) {
            const float4 kv = *(const float4*)&Cs[n * SST + d1b];
            const float4 vv = *(const float4*)&Cs[n * SST + 64 + d2b];
            m2[0][0] = fmaf(kv.x, vv.x, m2[0][0]);
            m2[0][1] = fmaf(kv.x, vv.y, m2[0][1]);
            m2[0][2] = fmaf(kv.x, vv.z, m2[0][2]);
            m2[0][3] = fmaf(kv.x, vv.w, m2[0][3]);
            m2[1][0] = fmaf(kv.y, vv.x, m2[1][0]);
            m2[1][1] = fmaf(kv.y, vv.y, m2[1][1]);
            m2[1][2] = fmaf(kv.y, vv.z, m2[1][2]);
            m2[1][3] = fmaf(kv.y, vv.w, m2[1][3]);
            m2[2][0] = fmaf(kv.z, vv.x, m2[2][0]);
            m2[2][1] = fmaf(kv.z, vv.y, m2[2][1]);
            m2[2][2] = fmaf(kv.z, vv.z, m2[2][2]);
            m2[2][3] = fmaf(kv.z, vv.w, m2[2][3]);
            m2[3][0] = fmaf(kv.w, vv.x, m2[3][0]);
            m2[3][1] = fmaf(kv.w, vv.y, m2[3][1]);
            m2[3][2] = fmaf(kv.w, vv.z, m2[3][2]);
            m2[3][3] = fmaf(kv.w, vv.w, m2[3][3]);
        }
#pragma unroll
        for (int i = 0; i < 4; i++) {
            float4 o = { m2[i][0], m2[i][1], m2[i][2], m2[i][3] };
            *(float4*)&g_Mpart[((by * 8 + hh) * 64 + d1b + i) * 64 + d2b] = o;
        }
    }
}

// ---------------------------------------------------------------------------
// K2: deterministic final reductions, float4 + deep MLP.
// blocks 0..63: M (each thread one float4 of 32768 floats).
// block 64: qsum (each thread one float4 of 512 floats).
// ---------------------------------------------------------------------------
__global__ __launch_bounds__(128)
void reduce_parts_kernel()
{
    if (blockIdx.x < 64) {
        const int idx = (blockIdx.x * 128 + threadIdx.x) * 4;   // 0..32764
        float4 s = {0.f, 0.f, 0.f, 0.f};
#pragma unroll
        for (int c = 0; c < NRB; c++) {
            const float4 v = *(const float4*)&g_Mpart[c * 32768 + idx];
            s.x += v.x; s.y += v.y; s.z += v.z; s.w += v.w;
        }
        *(float4*)&g_M[idx] = s;
    } else {
        const int idx = threadIdx.x * 4;                        // 0..508
        float4 s = {0.f, 0.f, 0.f, 0.f};
#pragma unroll
        for (int c = 0; c < NRB; c++) {
            const float4 v = *(const float4*)&g_qsumpart[c * 512 + idx];
            s.x += v.x; s.y += v.y; s.z += v.z; s.w += v.w;
        }
        *(float4*)&g_qsum[idx] = s;
    }
}

// ---------------------------------------------------------------------------
// K3: output + coarse. grid (32, 8), 128 threads, thread tile 8n x 8d2.
//   out[h,n,d2]  = scale * sum_d1 q_h[n,d1] * M_h[d1,d2]
//   coarse[h,n]  = scale * dot(qsum_h, k_h[n])
// ---------------------------------------------------------------------------
#define OUT_SMEM ((4096 + 8192 + 64) * 4)

__global__ __launch_bounds__(128)
void output_coarse_kernel(float* __restrict__ out)
{
    extern __shared__ float osm[];
    float (*Ms)[64] = (float(*)[64])osm;             // 64 x 64
    float (*qs)[64] = (float(*)[64])(osm + 4096);    // 128 x 64
    float* qsh = osm + 12288;                        // 64

    const int n0 = blockIdx.x * 128;
    const int h  = blockIdx.y;
    const int t  = threadIdx.x;

#pragma unroll
    for (int r = 0; r < 8; r++) {
        const int l = t + r * 128;
        *(float4*)&Ms[l >> 4][(l & 15) * 4] =
            *(const float4*)&g_M[h * 4096 + (l >> 4) * 64 + (l & 15) * 4];
    }
#pragma unroll
    for (int r = 0; r < 16; r++) {
        const int l = t + r * 128;
        *(float4*)&qs[l >> 4][(l & 15) * 4] =
            *(const float4*)&g_q[(size_t)(n0 + (l >> 4)) * 512 + h * 64 + (l & 15) * 4];
    }
    if (t < 64) qsh[t] = g_qsum[h * 64 + t];
    __syncthreads();

    const int tx = t & 7;        // d2 group (8 wide)
    const int ty = t >> 3;       // n group (8 rows)

    float acc[8][8];
#pragma unroll
    for (int i = 0; i < 8; i++)
#pragma unroll
        for (int j = 0; j < 8; j++) acc[i][j] = 0.0f;

#pragma unroll
    for (int d1 = 0; d1 < 64; d1++) {
        const float4 m0 = *(const float4*)&Ms[d1][tx * 8];
        const float4 m1 = *(const float4*)&Ms[d1][tx * 8 + 4];
#pragma unroll
        for (int i = 0; i < 8; i++) {
            const float qv = qs[ty * 8 + i][d1];
            acc[i][0] = fmaf(qv, m0.x, acc[i][0]);
            acc[i][1] = fmaf(qv, m0.y, acc[i][1]);
            acc[i][2] = fmaf(qv, m0.z, acc[i][2]);
            acc[i][3] = fmaf(qv, m0.w, acc[i][3]);
            acc[i][4] = fmaf(qv, m1.x, acc[i][4]);
            acc[i][5] = fmaf(qv, m1.y, acc[i][5]);
            acc[i][6] = fmaf(qv, m1.z, acc[i][6]);
            acc[i][7] = fmaf(qv, m1.w, acc[i][7]);
        }
    }

#pragma unroll
    for (int i = 0; i < 8; i++) {
        const int n = n0 + ty * 8 + i;
        float* ob = &out[32768 + (size_t)((h << 12) + n) * 64 + tx * 8];
        float4 o0 = { acc[i][0] * 0.125f, acc[i][1] * 0.125f,
                      acc[i][2] * 0.125f, acc[i][3] * 0.125f };
        float4 o1 = { acc[i][4] * 0.125f, acc[i][5] * 0.125f,
                      acc[i][6] * 0.125f, acc[i][7] * 0.125f };
        *(float4*)ob = o0;
        *(float4*)(ob + 4) = o1;
    }

    // coarse: one n per thread
    {
        const int n = n0 + t;
        const float4* kp = (const float4*)&g_k[(size_t)n * 512 + h * 64];
        float c = 0.0f;
#pragma unroll
        for (int i = 0; i < 16; i++) {
            const float4 k4 = kp[i];
            const float4 q4 = *(const float4*)&qsh[i * 4];
            c = fmaf(q4.x, k4.x, c); c = fmaf(q4.y, k4.y, c);
            c = fmaf(q4.z, k4.z, c); c = fmaf(q4.w, k4.w, c);
        }
        out[(h << 12) + n] = c * 0.125f;
    }
}

// ---------------------------------------------------------------------------
extern "C" void kernel_launch(void* const* d_in, const int* in_sizes, int n_in,
                              void* d_out, int out_size)
{
    const float* x  = (const float*)d_in[0];   // [512, 4096]
    const float* Wq = (const float*)d_in[1];   // [512, 1536]
    const float* bq = (const float*)d_in[2];   // [1536]
    float* out = (float*)d_out;
    (void)in_sizes; (void)n_in; (void)out_size;

    cudaFuncSetAttribute(fused_gemm, cudaFuncAttributeMaxDynamicSharedMemorySize, GEMM_SMEM);
    cudaFuncSetAttribute(output_coarse_kernel, cudaFuncAttributeMaxDynamicSharedMemorySize, OUT_SMEM);

    cvt_tf32_kernel<<<2816, 256>>>(x, Wq);     // X: 2048 blocks, W: 768 blocks

    fused_gemm<<<dim3(12, 32), 256, GEMM_SMEM>>>(bq);
    reduce_parts_kernel<<<65, 128>>>();
    output_coarse_kernel<<<dim3(32, 8), 128, OUT_SMEM>>>(out);
}